// round 2
// baseline (speedup 1.0000x reference)
#include <cuda_runtime.h>
#include <cstdint>

#define Bdim 64
#define Tdim 512
#define Idim 512
#define Hdim 1024
#define Gdim 4096
#define NCTA 128
#define NTHR 256

typedef unsigned long long ull;

// Scratch (allocation-free rule: __device__ globals)
__device__ float g_gates_x[(size_t)Tdim * Bdim * Gdim];  // [t][b][g], 512 MB
__device__ float g_h[2][Bdim * Hdim];                    // ping-pong hidden state
__device__ unsigned g_bar_cnt;

// ---------------- packed f32x2 helpers (full-rate fp32 FMA on sm_103a) ----------
__device__ __forceinline__ ull pack2(float x, float y) {
    ull r; asm("mov.b64 %0, {%1,%2};" : "=l"(r) : "f"(x), "f"(y)); return r;
}
__device__ __forceinline__ void unpack2(ull v, float& x, float& y) {
    asm("mov.b64 {%0,%1}, %2;" : "=f"(x), "=f"(y) : "l"(v));
}
__device__ __forceinline__ void ffma2(ull& d, ull a, ull b) {
    asm("fma.rn.f32x2 %0, %1, %2, %0;" : "+l"(d) : "l"(a), "l"(b));
}
__device__ __forceinline__ float sigmoidf_(float x) {
    return 1.0f / (1.0f + __expf(-x));
}

// ---------------- init: zero state + output + barrier ---------------------------
__global__ void init_state(float* __restrict__ out) {
    int i = blockIdx.x * blockDim.x + threadIdx.x;  // 65536 threads
    g_h[0][i] = 0.0f;
    g_h[1][i] = 0.0f;
    out[i] = 0.0f;
    if (i == 0) g_bar_cnt = 0u;
}

// ---------------- GEMM1: gates_x[t][b][g] = seq @ W_ih^T + (b_ih+b_hh) ----------
__global__ __launch_bounds__(256) void gates_x_gemm(
    const float* __restrict__ seq, const float* __restrict__ Wih,
    const float* __restrict__ bih, const float* __restrict__ bhh) {
    __shared__ float As[8][132];
    __shared__ float Bs[8][132];

    const int tid = threadIdx.x;
    const int tx = tid & 15;
    const int ty = tid >> 4;
    const int m0 = blockIdx.y * 128;
    const int n0 = blockIdx.x * 128;

    const int lr = tid >> 1;
    const int lk = (tid & 1) * 4;
    const float* aptr = seq + (size_t)(m0 + lr) * Idim + lk;
    const float* bptr = Wih + (size_t)(n0 + lr) * Idim + lk;

    ull acc[8][4];
#pragma unroll
    for (int i = 0; i < 8; i++)
#pragma unroll
        for (int j = 0; j < 4; j++) acc[i][j] = 0ull;

    for (int k0 = 0; k0 < Idim; k0 += 8) {
        float4 av = *(const float4*)(aptr + k0);
        float4 bv = *(const float4*)(bptr + k0);
        As[lk + 0][lr] = av.x; As[lk + 1][lr] = av.y;
        As[lk + 2][lr] = av.z; As[lk + 3][lr] = av.w;
        Bs[lk + 0][lr] = bv.x; Bs[lk + 1][lr] = bv.y;
        Bs[lk + 2][lr] = bv.z; Bs[lk + 3][lr] = bv.w;
        __syncthreads();
#pragma unroll
        for (int k = 0; k < 8; k++) {
            float4 a0 = *(const float4*)&As[k][ty * 8];
            float4 a1 = *(const float4*)&As[k][ty * 8 + 4];
            ull pb0 = *(const ull*)&Bs[k][tx * 8 + 0];
            ull pb1 = *(const ull*)&Bs[k][tx * 8 + 2];
            ull pb2 = *(const ull*)&Bs[k][tx * 8 + 4];
            ull pb3 = *(const ull*)&Bs[k][tx * 8 + 6];
            float am[8] = {a0.x, a0.y, a0.z, a0.w, a1.x, a1.y, a1.z, a1.w};
#pragma unroll
            for (int i = 0; i < 8; i++) {
                ull pa = pack2(am[i], am[i]);
                ffma2(acc[i][0], pa, pb0);
                ffma2(acc[i][1], pa, pb1);
                ffma2(acc[i][2], pa, pb2);
                ffma2(acc[i][3], pa, pb3);
            }
        }
        __syncthreads();
    }

#pragma unroll
    for (int i = 0; i < 8; i++) {
        int m = m0 + ty * 8 + i;
        int b = m >> 9;
        int t = m & 511;
        float* orow = g_gates_x + (size_t)(t * Bdim + b) * Gdim;
#pragma unroll
        for (int j = 0; j < 4; j++) {
            int n = n0 + tx * 8 + j * 2;
            float x, y; unpack2(acc[i][j], x, y);
            orow[n]     = x + bih[n]     + bhh[n];
            orow[n + 1] = y + bih[n + 1] + bhh[n + 1];
        }
    }
}

// ---------------- persistent recurrence kernel ----------------------------------
// 128 CTAs, 1 per SM (smem-limited) -> all co-resident, custom grid barrier safe.
// CTA jb owns hidden cols [jb*8, jb*8+8) = 32 gate rows. W_hh slice (32x1024 fp32,
// 144 KB padded) loaded to smem ONCE. c-state lives in smem for all 512 steps.
// h ping-pongs through global; one release/acquire grid barrier per step.
struct Smem {
    float W[Hdim][36];   // [k][n_local], row pad 36 for 16B-aligned LDS.128
    ull   hd[64][66];    // duplicated h pairs (h,h) per k-chunk, [kk][b]
    float pre[Bdim][33]; // pre-activations [b][n_local]
    float c[512];        // persistent cell state, [b*8+jj]
    int   lens[Bdim];
};

__device__ __forceinline__ void grid_barrier(int t) {
    __syncthreads();
    if (threadIdx.x == 0) {
        __threadfence();  // release h writes
        atomicAdd(&g_bar_cnt, 1u);
        unsigned target = (unsigned)(t + 1) * (unsigned)NCTA;
        while (*(volatile unsigned*)&g_bar_cnt < target) { }
        __threadfence();  // acquire
    }
    __syncthreads();
}

__global__ __launch_bounds__(NTHR, 1) void lstm_persistent(
    const float* __restrict__ Whh, const int* __restrict__ lens,
    float* __restrict__ out) {
    extern __shared__ char smem_raw[];
    Smem* S = (Smem*)smem_raw;

    const int tid = threadIdx.x;
    const int j0 = blockIdx.x * 8;

    // compute-thread mapping: npp in 0..7 -> n_local npp*4..npp*4+3 (2 pairs),
    // bq in 0..31 -> batches b0 = bq*2, b0+1
    const int npp4 = (tid & 7) * 4;
    const int b0 = (tid >> 3) * 2;

    // ---- one-time: load W_hh slice into smem (coalesced LDG, 4-way STS conflict ok)
    for (int idx = tid; idx < 32 * Hdim; idx += NTHR) {
        int k = idx & (Hdim - 1);
        int nl = idx >> 10;
        int row = (nl >> 3) * Hdim + j0 + (nl & 7);
        S->W[k][nl] = Whh[(size_t)row * Hdim + k];
    }
    if (tid < Bdim) S->lens[tid] = lens[tid];
    for (int i = tid; i < 512; i += NTHR) S->c[i] = 0.0f;
    __syncthreads();

    const int hb = tid >> 2;          // h-load: batch 0..63
    const int kq = (tid & 3) * 16;    //         k sub-segment

    for (int t = 0; t < Tdim; t++) {
        const float* hin  = g_h[t & 1];
        float*       hout = g_h[(t + 1) & 1];

        ull a00 = 0ull, a01 = 0ull, a10 = 0ull, a11 = 0ull;

        for (int k0 = 0; k0 < Hdim; k0 += 64) {
            // cooperative load of h chunk, duplicated into pairs
            const float4* hp = (const float4*)&hin[hb * Hdim + k0 + kq];
#pragma unroll
            for (int q = 0; q < 4; q++) {
                float4 v = hp[q];
                int kk = kq + q * 4;
                S->hd[kk + 0][hb] = pack2(v.x, v.x);
                S->hd[kk + 1][hb] = pack2(v.y, v.y);
                S->hd[kk + 2][hb] = pack2(v.z, v.z);
                S->hd[kk + 3][hb] = pack2(v.w, v.w);
            }
            __syncthreads();
#pragma unroll 16
            for (int kk = 0; kk < 64; kk++) {
                const float* wr = &S->W[k0 + kk][npp4];
                ull w0 = *(const ull*)(wr);
                ull w1 = *(const ull*)(wr + 2);
                longlong2 hv = *(const longlong2*)&S->hd[kk][b0];
                ull p0 = (ull)hv.x, p1 = (ull)hv.y;
                ffma2(a00, p0, w0);
                ffma2(a01, p0, w1);
                ffma2(a10, p1, w0);
                ffma2(a11, p1, w1);
            }
            __syncthreads();
        }

        // epilogue: add gates_x, stage pre-activations
        const float* gx = g_gates_x + (size_t)(t * Bdim) * Gdim;
        {
            float x, y;
            int r0 = ((npp4 + 0) >> 3) * Hdim + j0 + ((npp4 + 0) & 7);
            int r1 = ((npp4 + 1) >> 3) * Hdim + j0 + ((npp4 + 1) & 7);
            int r2 = ((npp4 + 2) >> 3) * Hdim + j0 + ((npp4 + 2) & 7);
            int r3 = ((npp4 + 3) >> 3) * Hdim + j0 + ((npp4 + 3) & 7);
            const float* gb0 = gx + (size_t)b0 * Gdim;
            const float* gb1 = gx + (size_t)(b0 + 1) * Gdim;
            unpack2(a00, x, y);
            S->pre[b0][npp4 + 0] = x + gb0[r0];
            S->pre[b0][npp4 + 1] = y + gb0[r1];
            unpack2(a01, x, y);
            S->pre[b0][npp4 + 2] = x + gb0[r2];
            S->pre[b0][npp4 + 3] = y + gb0[r3];
            unpack2(a10, x, y);
            S->pre[b0 + 1][npp4 + 0] = x + gb1[r0];
            S->pre[b0 + 1][npp4 + 1] = y + gb1[r1];
            unpack2(a11, x, y);
            S->pre[b0 + 1][npp4 + 2] = x + gb1[r2];
            S->pre[b0 + 1][npp4 + 3] = y + gb1[r3];
        }
        __syncthreads();

        // pointwise cell update: 512 (b, jj) pairs, 2 per thread
#pragma unroll
        for (int r = 0; r < 2; r++) {
            int p = r * NTHR + tid;   // 0..511
            int b = p >> 3;
            int jj = p & 7;
            float xi = S->pre[b][0 + jj];
            float xf = S->pre[b][8 + jj];
            float xg = S->pre[b][16 + jj];
            float xo = S->pre[b][24 + jj];
            float si = sigmoidf_(xi);
            float sf = sigmoidf_(xf);
            float tg = tanhf(xg);
            float so = sigmoidf_(xo);
            float c_new = sf * S->c[p] + si * tg;
            float h_new = so * tanhf(c_new);
            S->c[p] = c_new;
            int gidx = b * Hdim + j0 + jj;
            hout[gidx] = h_new;
            if (S->lens[b] > t) out[gidx] = h_new;
        }

        grid_barrier(t);
    }
}

// ---------------- launch ---------------------------------------------------------
extern "C" void kernel_launch(void* const* d_in, const int* in_sizes, int n_in,
                              void* d_out, int out_size) {
    const float* seq  = (const float*)d_in[0];
    const int*   lensp = (const int*)d_in[1];
    const float* Wih  = (const float*)d_in[2];
    const float* Whh  = (const float*)d_in[3];
    const float* bih  = (const float*)d_in[4];
    const float* bhh  = (const float*)d_in[5];
    float* out = (float*)d_out;

    cudaFuncSetAttribute(lstm_persistent,
                         cudaFuncAttributeMaxDynamicSharedMemorySize,
                         (int)sizeof(Smem));

    init_state<<<256, 256>>>(out);

    dim3 g1(Gdim / 128, (Bdim * Tdim) / 128);
    gates_x_gemm<<<g1, 256>>>(seq, Wih, bih, bhh);

    lstm_persistent<<<NCTA, NTHR, sizeof(Smem)>>>(Whh, lensp, out);
}

// round 4
// speedup vs baseline: 2.7315x; 2.7315x over previous
#include <cuda_runtime.h>
#include <cuda_bf16.h>
#include <cstdint>

#define Bdim 64
#define Tdim 512
#define Idim 512
#define Hdim 1024
#define Gdim 4096
#define NCTA 128

typedef unsigned long long ull;

// ---------------- device globals (allocation-free scratch) ----------------------
__device__ float g_gates_x[(size_t)Tdim * Bdim * Gdim];          // [t][b][4096]
__device__ __nv_bfloat16 g_h[2][2][Bdim][Hdim];                  // [pp][hi/lo][b][k]
__device__ __nv_bfloat16 g_W_img[NCTA][2][32][Hdim];             // [jb][hi/lo][nl][k]
__device__ float g_c[NCTA][Bdim][8];                             // cell state

// ---------------- helpers --------------------------------------------------------
__device__ __forceinline__ uint32_t smem_u32(const void* p) {
    uint32_t a;
    asm("{ .reg .u64 t; cvta.to.shared.u64 t, %1; cvt.u32.u64 %0, t; }" : "=r"(a) : "l"(p));
    return a;
}
__device__ __forceinline__ void cp16(uint32_t dst, const void* src) {
    asm volatile("cp.async.ca.shared.global [%0], [%1], 16;" :: "r"(dst), "l"(src) : "memory");
}
__device__ __forceinline__ void cp_commit() {
    asm volatile("cp.async.commit_group;" ::: "memory");
}
template <int N>
__device__ __forceinline__ void cp_wait() {
    asm volatile("cp.async.wait_group %0;" :: "n"(N) : "memory");
}
__device__ __forceinline__ void ldm_x4(uint32_t& r0, uint32_t& r1, uint32_t& r2,
                                       uint32_t& r3, uint32_t addr) {
    asm volatile("ldmatrix.sync.aligned.m8n8.x4.shared.b16 {%0,%1,%2,%3}, [%4];"
                 : "=r"(r0), "=r"(r1), "=r"(r2), "=r"(r3) : "r"(addr));
}
__device__ __forceinline__ void mma_bf16(float* c, uint32_t a0, uint32_t a1,
                                         uint32_t a2, uint32_t a3,
                                         uint32_t b0, uint32_t b1) {
    asm volatile(
        "mma.sync.aligned.m16n8k16.row.col.f32.bf16.bf16.f32 "
        "{%0,%1,%2,%3}, {%4,%5,%6,%7}, {%8,%9}, {%0,%1,%2,%3};"
        : "+f"(c[0]), "+f"(c[1]), "+f"(c[2]), "+f"(c[3])
        : "r"(a0), "r"(a1), "r"(a2), "r"(a3), "r"(b0), "r"(b1));
}
__device__ __forceinline__ ull pack2(float x, float y) {
    ull r; asm("mov.b64 %0, {%1,%2};" : "=l"(r) : "f"(x), "f"(y)); return r;
}
__device__ __forceinline__ void unpack2(ull v, float& x, float& y) {
    asm("mov.b64 {%0,%1}, %2;" : "=f"(x), "=f"(y) : "l"(v));
}
__device__ __forceinline__ void ffma2(ull& d, ull a, ull b) {
    asm("fma.rn.f32x2 %0, %1, %2, %0;" : "+l"(d) : "l"(a), "l"(b));
}
__device__ __forceinline__ float sigm_(float x) {
    return __fdividef(1.0f, 1.0f + __expf(-x));
}
__device__ __forceinline__ float tanh_(float x) {
    return 1.0f - __fdividef(2.0f, __expf(2.0f * x) + 1.0f);
}

// ---------------- init ------------------------------------------------------------
__global__ void init_state(float* __restrict__ out) {
    int i = blockIdx.x * blockDim.x + threadIdx.x;  // 65536 threads
    ((uint32_t*)g_h[0])[i] = 0u;     // zero both planes of pp=0 (256KB = 65536 u32)
    ((float*)g_c)[i] = 0.0f;         // 65536 floats
    out[i] = 0.0f;
}

// ---------------- W_hh -> per-CTA bf16 hi/lo image ---------------------------------
__global__ __launch_bounds__(256) void w_prep(const float* __restrict__ Whh) {
    int bid = blockIdx.x;            // 4096 = 128 jb x 32 nl
    int jb = bid >> 5;
    int nl = bid & 31;
    int grow = (nl >> 3) * Hdim + jb * 8 + (nl & 7);
    const float* src = Whh + (size_t)grow * Hdim;
#pragma unroll
    for (int q = 0; q < 4; q++) {
        int k = q * 256 + threadIdx.x;
        float w = src[k];
        __nv_bfloat16 hi = __float2bfloat16(w);
        __nv_bfloat16 lo = __float2bfloat16(w - __bfloat162float(hi));
        g_W_img[jb][0][nl][k] = hi;
        g_W_img[jb][1][nl][k] = lo;
    }
}

// ---------------- GEMM1 (fp32x2 SIMT, unchanged) -----------------------------------
__global__ __launch_bounds__(256) void gates_x_gemm(
    const float* __restrict__ seq, const float* __restrict__ Wih,
    const float* __restrict__ bih, const float* __restrict__ bhh) {
    __shared__ float As[8][132];
    __shared__ float Bs[8][132];

    const int tid = threadIdx.x;
    const int tx = tid & 15;
    const int ty = tid >> 4;
    const int m0 = blockIdx.y * 128;
    const int n0 = blockIdx.x * 128;

    const int lr = tid >> 1;
    const int lk = (tid & 1) * 4;
    const float* aptr = seq + (size_t)(m0 + lr) * Idim + lk;
    const float* bptr = Wih + (size_t)(n0 + lr) * Idim + lk;

    ull acc[8][4];
#pragma unroll
    for (int i = 0; i < 8; i++)
#pragma unroll
        for (int j = 0; j < 4; j++) acc[i][j] = 0ull;

    for (int k0 = 0; k0 < Idim; k0 += 8) {
        float4 av = *(const float4*)(aptr + k0);
        float4 bv = *(const float4*)(bptr + k0);
        As[lk + 0][lr] = av.x; As[lk + 1][lr] = av.y;
        As[lk + 2][lr] = av.z; As[lk + 3][lr] = av.w;
        Bs[lk + 0][lr] = bv.x; Bs[lk + 1][lr] = bv.y;
        Bs[lk + 2][lr] = bv.z; Bs[lk + 3][lr] = bv.w;
        __syncthreads();
#pragma unroll
        for (int k = 0; k < 8; k++) {
            float4 a0 = *(const float4*)&As[k][ty * 8];
            float4 a1 = *(const float4*)&As[k][ty * 8 + 4];
            ull pb0 = *(const ull*)&Bs[k][tx * 8 + 0];
            ull pb1 = *(const ull*)&Bs[k][tx * 8 + 2];
            ull pb2 = *(const ull*)&Bs[k][tx * 8 + 4];
            ull pb3 = *(const ull*)&Bs[k][tx * 8 + 6];
            float am[8] = {a0.x, a0.y, a0.z, a0.w, a1.x, a1.y, a1.z, a1.w};
#pragma unroll
            for (int i = 0; i < 8; i++) {
                ull pa = pack2(am[i], am[i]);
                ffma2(acc[i][0], pa, pb0);
                ffma2(acc[i][1], pa, pb1);
                ffma2(acc[i][2], pa, pb2);
                ffma2(acc[i][3], pa, pb3);
            }
        }
        __syncthreads();
    }

#pragma unroll
    for (int i = 0; i < 8; i++) {
        int m = m0 + ty * 8 + i;
        int b = m >> 9;
        int t = m & 511;
        float* orow = g_gates_x + (size_t)(t * Bdim + b) * Gdim;
#pragma unroll
        for (int j = 0; j < 4; j++) {
            int n = n0 + tx * 8 + j * 2;
            float x, y; unpack2(acc[i][j], x, y);
            orow[n]     = x + bih[n]     + bhh[n];
            orow[n + 1] = y + bih[n + 1] + bhh[n + 1];
        }
    }
}

// ---------------- per-step HMMA kernel ---------------------------------------------
// grid=128 CTAs x 256 thr. CTA jb: gates[64 x 32] = h[64 x 1024] @ Wslice^T,
// split-bf16 (3 mma terms), K chunked x128, cp.async double-buffered.
// Warp w: m-tile mt=w&3 (batches mt*16..+15), n-half nh=w>>2 (n-tiles 2nh, 2nh+1).
#define KC 128
#define NCHUNK 8
// smem layout (bytes): h[buf][plane][64][136]bf16, w[buf][plane][32][136]bf16, pre
#define HROW 272            // 136 bf16 row pitch (conflict-free for ldmatrix)
#define HPLANE (64 * HROW)  // 17408
#define HBUF (2 * HPLANE)   // 34816
#define WPLANE (32 * HROW)  // 8704
#define WBUF (2 * WPLANE)   // 17408
#define OFF_H 0
#define OFF_W (2 * HBUF)             // 69632
#define OFF_PRE (OFF_W + 2 * WBUF)   // 104448
#define SMEM_BYTES (OFF_PRE + 64 * 36 * 4)  // 113664

__global__ __launch_bounds__(256) void lstm_step_mma(
    const int* __restrict__ lens, float* __restrict__ out, int t) {
    extern __shared__ unsigned char smem[];
    const uint32_t sb = smem_u32(smem);
    float* pre = (float*)(smem + OFF_PRE);  // [64][36]

    const int tid = threadIdx.x;
    const int lane = tid & 31;
    const int w = tid >> 5;
    const int jb = blockIdx.x;
    const int j0 = jb * 8;
    const int pp = t & 1;

    // ---- early prefetches for the pointwise tail (threads 0-63, b = tid)
    float gxi[8], gxf[8], gxg[8], gxo[8], cst[8];
    int lb = 0;
    if (tid < 64) {
        const float* gxb = g_gates_x + ((size_t)t * Bdim + tid) * Gdim + j0;
#pragma unroll
        for (int g = 0; g < 4; g++) {
            float4 v0 = *(const float4*)(gxb + g * Hdim);
            float4 v1 = *(const float4*)(gxb + g * Hdim + 4);
            float* dstp = (g == 0) ? gxi : (g == 1) ? gxf : (g == 2) ? gxg : gxo;
            dstp[0] = v0.x; dstp[1] = v0.y; dstp[2] = v0.z; dstp[3] = v0.w;
            dstp[4] = v1.x; dstp[5] = v1.y; dstp[6] = v1.z; dstp[7] = v1.w;
        }
        float4 c0 = *(const float4*)&g_c[jb][tid][0];
        float4 c1 = *(const float4*)&g_c[jb][tid][4];
        cst[0] = c0.x; cst[1] = c0.y; cst[2] = c0.z; cst[3] = c0.w;
        cst[4] = c1.x; cst[5] = c1.y; cst[6] = c1.z; cst[7] = c1.w;
        lb = lens[tid];
    }

    // ---- per-lane ldmatrix base offsets
    const int mt = w & 3;
    const int nh = w >> 2;
    const uint32_t a_off = (uint32_t)((mt * 16 + (lane & 7) + ((lane >> 3) & 1) * 8) * HROW
                                      + ((lane >> 4) & 1) * 16);
    const uint32_t b_off = (uint32_t)((nh * 16 + ((lane >> 4) & 1) * 8 + (lane & 7)) * HROW
                                      + ((lane >> 3) & 1) * 16);

    float C[2][4] = {{0.f, 0.f, 0.f, 0.f}, {0.f, 0.f, 0.f, 0.f}};

    // ---- copy helper (chunk kc -> buffer kc&1)
    auto issue_chunk = [&](int kc) {
        int buf = kc & 1;
        const __nv_bfloat16* hsrc = &g_h[pp][0][0][0];
#pragma unroll
        for (int q = 0; q < 8; q++) {       // h: 2048 x 16B ops
            int i = q * 256 + tid;
            int seg = i & 15;
            int rp = i >> 4;                // 0..127
            int plane = rp >> 6, b = rp & 63;
            const void* src = hsrc + ((size_t)plane * Bdim + b) * Hdim + kc * KC + seg * 8;
            uint32_t dst = sb + OFF_H + buf * HBUF + plane * HPLANE + b * HROW + seg * 16;
            cp16(dst, src);
        }
        const __nv_bfloat16* wsrc = &g_W_img[jb][0][0][0];
#pragma unroll
        for (int q = 0; q < 4; q++) {       // w: 1024 x 16B ops
            int i = q * 256 + tid;
            int seg = i & 15;
            int rp = i >> 4;                // 0..63
            int plane = rp >> 5, nl = rp & 31;
            const void* src = wsrc + ((size_t)plane * 32 + nl) * Hdim + kc * KC + seg * 8;
            uint32_t dst = sb + OFF_W + buf * WBUF + plane * WPLANE + nl * HROW + seg * 16;
            cp16(dst, src);
        }
        cp_commit();
    };

    issue_chunk(0);

    for (int kc = 0; kc < NCHUNK; kc++) {
        if (kc + 1 < NCHUNK) { issue_chunk(kc + 1); cp_wait<1>(); }
        else                 { cp_wait<0>(); }
        __syncthreads();

        int buf = kc & 1;
        uint32_t ha = sb + OFF_H + buf * HBUF + a_off;
        uint32_t wa = sb + OFF_W + buf * WBUF + b_off;
#pragma unroll
        for (int ks = 0; ks < KC / 16; ks++) {
            uint32_t ah0, ah1, ah2, ah3, al0, al1, al2, al3;
            uint32_t bh0, bh1, bh2, bh3, bl0, bl1, bl2, bl3;
            ldm_x4(ah0, ah1, ah2, ah3, ha + ks * 32);
            ldm_x4(al0, al1, al2, al3, ha + HPLANE + ks * 32);
            ldm_x4(bh0, bh1, bh2, bh3, wa + ks * 32);
            ldm_x4(bl0, bl1, bl2, bl3, wa + WPLANE + ks * 32);
            mma_bf16(C[0], ah0, ah1, ah2, ah3, bh0, bh1);   // hi*hi
            mma_bf16(C[1], ah0, ah1, ah2, ah3, bh2, bh3);
            mma_bf16(C[0], ah0, ah1, ah2, ah3, bl0, bl1);   // hi*lo
            mma_bf16(C[1], ah0, ah1, ah2, ah3, bl2, bl3);
            mma_bf16(C[0], al0, al1, al2, al3, bh0, bh1);   // lo*hi
            mma_bf16(C[1], al0, al1, al2, al3, bh2, bh3);
        }
        __syncthreads();
    }

    // ---- stage C fragments to pre[64][36]
    {
        int g = lane >> 2, t2 = (lane & 3) * 2;
        int m = mt * 16 + g;
#pragma unroll
        for (int nt = 0; nt < 2; nt++) {
            int n = (nh * 2 + nt) * 8 + t2;
            *(float2*)&pre[m * 36 + n]       = make_float2(C[nt][0], C[nt][1]);
            *(float2*)&pre[(m + 8) * 36 + n] = make_float2(C[nt][2], C[nt][3]);
        }
    }
    __syncthreads();

    // ---- pointwise LSTM cell (threads 0-63, b = tid)
    if (tid < 64) {
        int b = tid;
        float hn[8];
        unsigned short hu[8], lu[8];
#pragma unroll
        for (int jj = 0; jj < 8; jj++) {
            float xi = pre[b * 36 + jj]      + gxi[jj];
            float xf = pre[b * 36 + 8 + jj]  + gxf[jj];
            float xg = pre[b * 36 + 16 + jj] + gxg[jj];
            float xo = pre[b * 36 + 24 + jj] + gxo[jj];
            float i_ = sigm_(xi), f_ = sigm_(xf), g_ = tanh_(xg), o_ = sigm_(xo);
            float cn = f_ * cst[jj] + i_ * g_;
            cst[jj] = cn;
            float h = o_ * tanh_(cn);
            hn[jj] = h;
            __nv_bfloat16 hh = __float2bfloat16(h);
            __nv_bfloat16 hl = __float2bfloat16(h - __bfloat162float(hh));
            hu[jj] = __bfloat16_as_ushort(hh);
            lu[jj] = __bfloat16_as_ushort(hl);
        }
        *(float4*)&g_c[jb][b][0] = make_float4(cst[0], cst[1], cst[2], cst[3]);
        *(float4*)&g_c[jb][b][4] = make_float4(cst[4], cst[5], cst[6], cst[7]);

        uint4 vh, vl;
        vh.x = (uint32_t)hu[0] | ((uint32_t)hu[1] << 16);
        vh.y = (uint32_t)hu[2] | ((uint32_t)hu[3] << 16);
        vh.z = (uint32_t)hu[4] | ((uint32_t)hu[5] << 16);
        vh.w = (uint32_t)hu[6] | ((uint32_t)hu[7] << 16);
        vl.x = (uint32_t)lu[0] | ((uint32_t)lu[1] << 16);
        vl.y = (uint32_t)lu[2] | ((uint32_t)lu[3] << 16);
        vl.z = (uint32_t)lu[4] | ((uint32_t)lu[5] << 16);
        vl.w = (uint32_t)lu[6] | ((uint32_t)lu[7] << 16);
        int pp1 = (t + 1) & 1;
        *(uint4*)&g_h[pp1][0][b][j0] = vh;
        *(uint4*)&g_h[pp1][1][b][j0] = vl;

        if (lb > t) {
            float* ob = out + (size_t)b * Hdim + j0;
            *(float4*)(ob)     = make_float4(hn[0], hn[1], hn[2], hn[3]);
            *(float4*)(ob + 4) = make_float4(hn[4], hn[5], hn[6], hn[7]);
        }
    }
}

// ---------------- launch ------------------------------------------------------------
extern "C" void kernel_launch(void* const* d_in, const int* in_sizes, int n_in,
                              void* d_out, int out_size) {
    const float* seq   = (const float*)d_in[0];
    const int*   lensp = (const int*)d_in[1];
    const float* Wih   = (const float*)d_in[2];
    const float* Whh   = (const float*)d_in[3];
    const float* bih   = (const float*)d_in[4];
    const float* bhh   = (const float*)d_in[5];
    float* out = (float*)d_out;

    cudaFuncSetAttribute(lstm_step_mma,
                         cudaFuncAttributeMaxDynamicSharedMemorySize, SMEM_BYTES);

    init_state<<<256, 256>>>(out);
    w_prep<<<4096, 256>>>(Whh);

    dim3 g1(Gdim / 128, (Bdim * Tdim) / 128);
    gates_x_gemm<<<g1, 256>>>(seq, Wih, bih, bhh);

    for (int t = 0; t < Tdim; t++) {
        lstm_step_mma<<<NCTA, 256, SMEM_BYTES>>>(lensp, out, t);
    }
}